// round 12
// baseline (speedup 1.0000x reference)
#include <cuda_runtime.h>
#include <cstdint>

#define NV 10000
#define NR 8
#define NC 64
#define NU 64
#define ROWS 128
#define NTHREADS 256

// ---- smem layout (bytes) ----
#define A_BUF  32768                 // 128 rows * 256B, swizzled stride-64
#define B_PAD  72                    // floats per B row (bank-conflict-free)
#define B_BUF  18432                 // 64 rows * 288B fp32
#define OFF_A  0
#define OFF_B  (2*A_BUF)             // 65536
#define SMEM_BYTES (OFF_B + 2*B_BUF) // 102400 -> 2 CTA/SM

__device__ __align__(16) float g_zero[64] = {};

// ---------------- helpers ----------------
__device__ __forceinline__ unsigned cvta_smem(const void* p) {
    unsigned r;
    asm("{ .reg .u64 t; cvta.to.shared.u64 t, %1; cvt.u32.u64 %0, t; }"
        : "=r"(r) : "l"(p));
    return r;
}
__device__ __forceinline__ void cpasync16(unsigned dst, const void* src) {
    asm volatile("cp.async.cg.shared.global [%0], [%1], 16;" :: "r"(dst), "l"(src));
}
#define CP_COMMIT() asm volatile("cp.async.commit_group;" ::: "memory")
#define CP_WAIT(n)  asm volatile("cp.async.wait_group %0;" :: "n"(n) : "memory")

__device__ __forceinline__ unsigned cvt_tf32(float f) {
    unsigned t;
    asm("cvt.rna.tf32.f32 %0, %1;" : "=r"(t) : "f"(f));
    return t;
}
__device__ __forceinline__ void ldsm_x4(unsigned addr, unsigned& r0, unsigned& r1,
                                        unsigned& r2, unsigned& r3) {
    asm volatile("ldmatrix.sync.aligned.m8n8.x4.shared.b16 {%0,%1,%2,%3}, [%4];"
                 : "=r"(r0), "=r"(r1), "=r"(r2), "=r"(r3) : "r"(addr));
}
__device__ __forceinline__ void mma_tf32(float& d0, float& d1, float& d2, float& d3,
                                         unsigned a0, unsigned a1, unsigned a2, unsigned a3,
                                         unsigned b0, unsigned b1) {
    asm volatile("mma.sync.aligned.m16n8k8.row.col.f32.tf32.tf32.f32 "
                 "{%0,%1,%2,%3}, {%4,%5,%6,%7}, {%8,%9}, {%0,%1,%2,%3};"
                 : "+f"(d0), "+f"(d1), "+f"(d2), "+f"(d3)
                 : "r"(a0), "r"(a1), "r"(a2), "r"(a3), "r"(b0), "r"(b1));
}
__device__ __forceinline__ unsigned long long fma2(unsigned long long a,
                                                   unsigned long long b,
                                                   unsigned long long c) {
    unsigned long long d;
    asm("fma.rn.f32x2 %0, %1, %2, %3;" : "=l"(d) : "l"(a), "l"(b), "l"(c));
    return d;
}
__device__ __forceinline__ unsigned long long bcast2(float x) {
    unsigned long long d;
    asm("mov.b64 %0, {%1, %1};" : "=l"(d) : "f"(x));
    return d;
}
__device__ __forceinline__ float2 unpack2(unsigned long long v) {
    float2 f;
    asm("mov.b64 {%0, %1}, %2;" : "=f"(f.x), "=f"(f.y) : "l"(v));
    return f;
}

__global__ void __launch_bounds__(NTHREADS, 2)
graphconv_ws(const float* __restrict__ nodes,
             const int*   __restrict__ mapping,
             const float* __restrict__ kern,
             const float* __restrict__ bias,
             float*       __restrict__ out)
{
    extern __shared__ char smem[];
    const unsigned smem_u = cvta_smem(smem);

    const int tid  = threadIdx.x;
    const int row0 = blockIdx.x * ROWS;
    const int wid  = tid >> 5;
    const int l    = tid & 31;

    // gather roles: 2 lanes per row
    const int gm   = tid >> 1;           // local row 0..127
    const int gl   = tid & 1;
    const int grow = row0 + gm;
    const int bV   = (grow / NV) * NV;

    // accumulators: a thread is EITHER tensor or FFMA -> share storage
    union Acc {
        float d[32];                     // tensor: d[nt*4+q], nt 0..7
        unsigned long long e[16];        // ffma:   e[i*2+h],  i 0..7
    } acc;
#pragma unroll
    for (int i = 0; i < 32; ++i) acc.d[i] = 0.f;

    int m_cur = __ldg(mapping + (size_t)grow * NR);

    // ---- prologue: region 0 (pure cp.async staging) ----
    {
        const float* src = (m_cur >= 0) ? nodes + ((size_t)(bV + m_cur) << 6) : g_zero;
        unsigned dA = smem_u + OFF_A + (unsigned)(gm * 256);
#pragma unroll
        for (int j = 0; j < 8; ++j) {
            const int jj = gl * 8 + j;
            cpasync16(dA + (unsigned)((jj ^ (gm & 7)) << 4), src + jj * 4);
        }
        // B: 64 rows x 16 chunks (16B), padded rows of 288B
#pragma unroll
        for (int i = 0; i < 4; ++i) {
            const int c = tid + i * NTHREADS;    // 0..1023
            const int k = c >> 4, ch = c & 15;
            cpasync16(smem_u + OFF_B + (unsigned)(k * 288 + ch * 16),
                      kern + k * NU + ch * 4);
        }
        CP_COMMIT();
    }
    int m_nxt = __ldg(mapping + (size_t)grow * NR + 1);

#pragma unroll 1
    for (int r = 0; r < NR; ++r) {
        const int buf = r & 1;

        // ---- stage region r+1 (pure cp.async) ----
        if (r < NR - 1) {
            const int nb = buf ^ 1;
            const float* kg = kern + (size_t)(r + 1) * (NC * NU);
            const float* src = (m_nxt >= 0) ? nodes + ((size_t)(bV + m_nxt) << 6) : g_zero;
            unsigned dA = smem_u + OFF_A + (unsigned)(nb * A_BUF + gm * 256);
#pragma unroll
            for (int j = 0; j < 8; ++j) {
                const int jj = gl * 8 + j;
                cpasync16(dA + (unsigned)((jj ^ (gm & 7)) << 4), src + jj * 4);
            }
#pragma unroll
            for (int i = 0; i < 4; ++i) {
                const int c = tid + i * NTHREADS;
                const int k = c >> 4, ch = c & 15;
                cpasync16(smem_u + OFF_B + (unsigned)(nb * B_BUF + k * 288 + ch * 16),
                          kg + k * NU + ch * 4);
            }
            CP_COMMIT();
            if (r < NR - 2) m_nxt = __ldg(mapping + (size_t)grow * NR + r + 2);
        }

        if (r < NR - 1) { CP_WAIT(1); } else { CP_WAIT(0); }
        __syncthreads();

        if (wid < 4) {
            // ================= tensor warps: rows wid*16 .. +15, full K =========
            const float* Bb = (const float*)(smem + OFF_B + buf * B_BUF)
                            + (l & 3) * B_PAD + (l >> 2);
            const unsigned a_ld = smem_u + OFF_A
                + (unsigned)(buf * A_BUF + (wid * 16 + (l & 15)) * 256);
            const int rx = l & 7;

#pragma unroll
            for (int ks = 0; ks < 8; ++ks) {
                const float* Bk = Bb + ks * 8 * B_PAD;
                unsigned b0[8], b1[8];
#pragma unroll
                for (int nt = 0; nt < 8; ++nt) {
                    b0[nt] = cvt_tf32(Bk[nt * 8]);
                    b1[nt] = cvt_tf32(Bk[4 * B_PAD + nt * 8]);
                }
                unsigned a0, a1, a2, a3;
                ldsm_x4(a_ld + (unsigned)((((ks * 2 + (l >> 4)) ^ rx) << 4)),
                        a0, a1, a2, a3);
                a0 = cvt_tf32(__uint_as_float(a0));
                a1 = cvt_tf32(__uint_as_float(a1));
                a2 = cvt_tf32(__uint_as_float(a2));
                a3 = cvt_tf32(__uint_as_float(a3));
#pragma unroll
                for (int nt = 0; nt < 8; ++nt)
                    mma_tf32(acc.d[nt*4+0], acc.d[nt*4+1], acc.d[nt*4+2], acc.d[nt*4+3],
                             a0, a1, a2, a3, b0[nt], b1[nt]);
            }
        } else {
            // ================= FFMA2 warps: rows 64 + (wid-4)*16 .. +15, full K =
            const int fw = wid - 4;
            const int ux = l & 15;
            const int ry = l >> 4;
            const int base_l = 64 + fw * 16 + ry;
            const float* B2 = (const float*)(smem + OFF_B + buf * B_BUF) + ux * 4;

#pragma unroll
            for (int kb4 = 0; kb4 < 16; ++kb4) {
                ulonglong2 b[4];
#pragma unroll
                for (int kk = 0; kk < 4; ++kk)
                    b[kk] = *(const ulonglong2*)(B2 + (kb4 * 4 + kk) * B_PAD);
#pragma unroll
                for (int i = 0; i < 8; ++i) {
                    const int rl = base_l + 2 * i;
                    const float4 a = *(const float4*)
                        (smem + (buf * A_BUF + rl * 256 + (((kb4 ^ (rl & 7)) << 4))));
                    const float af[4] = {a.x, a.y, a.z, a.w};
#pragma unroll
                    for (int kk = 0; kk < 4; ++kk) {
                        unsigned long long ax = bcast2(af[kk]);
                        acc.e[i*2+0] = fma2(ax, b[kk].x, acc.e[i*2+0]);
                        acc.e[i*2+1] = fma2(ax, b[kk].y, acc.e[i*2+1]);
                    }
                }
            }
        }
        __syncthreads();   // all warps done reading buf before refill
    }

    // ---- epilogue ----
    if (wid < 4) {
#pragma unroll
        for (int nt = 0; nt < 8; ++nt) {
            const int u0 = nt * 8 + 2 * (l & 3);
            float2 bv = *(const float2*)(bias + u0);
            const int rA = row0 + wid * 16 + (l >> 2);
            float2 o0, o1;
            o0.x = fmaxf(acc.d[nt*4+0] + bv.x, 0.f);
            o0.y = fmaxf(acc.d[nt*4+1] + bv.y, 0.f);
            o1.x = fmaxf(acc.d[nt*4+2] + bv.x, 0.f);
            o1.y = fmaxf(acc.d[nt*4+3] + bv.y, 0.f);
            *(float2*)(out + (size_t)rA * NU + u0)       = o0;
            *(float2*)(out + (size_t)(rA + 8) * NU + u0) = o1;
        }
    } else {
        const int fw = wid - 4;
        const int ux = l & 15;
        const int ry = l >> 4;
        float4 bv = ((const float4*)bias)[ux];
#pragma unroll
        for (int i = 0; i < 8; ++i) {
            const int rA = row0 + 64 + fw * 16 + ry + 2 * i;
            float2 e0 = unpack2(acc.e[i*2+0]);
            float2 e1 = unpack2(acc.e[i*2+1]);
            float4 o;
            o.x = fmaxf(e0.x + bv.x, 0.f);
            o.y = fmaxf(e0.y + bv.y, 0.f);
            o.z = fmaxf(e1.x + bv.z, 0.f);
            o.w = fmaxf(e1.y + bv.w, 0.f);
            *(float4*)(out + (size_t)rA * NU + ux * 4) = o;
        }
    }
}

extern "C" void kernel_launch(void* const* d_in, const int* in_sizes, int n_in,
                              void* d_out, int out_size) {
    (void)in_sizes; (void)n_in; (void)out_size;
    const float* nodes   = (const float*)d_in[0];
    const int*   mapping = (const int*)d_in[1];
    const float* kern    = (const float*)d_in[2];
    const float* bias    = (const float*)d_in[3];
    float*       out     = (float*)d_out;

    cudaFuncSetAttribute(graphconv_ws,
                         cudaFuncAttributeMaxDynamicSharedMemorySize, SMEM_BYTES);

    int grid = (16 * NV) / ROWS;   // 1250
    graphconv_ws<<<grid, NTHREADS, SMEM_BYTES>>>(nodes, mapping, kern, bias, out);
}

// round 13
// speedup vs baseline: 1.5887x; 1.5887x over previous
#include <cuda_runtime.h>
#include <cstdint>

#define NV 10000
#define NR 8
#define NC 64
#define NU 64

#define ROWS 128
#define NTHREADS 256
#define APAD 68                       // A fp32 row stride (conflict-free for ldsm)
#define BPAD 72                       // B fp32 row stride (conflict-free scalar loads)

#define SA_FLOATS (ROWS * APAD)       // 8704 per buffer
#define SB_FLOATS (NC * BPAD)         // 4608 per buffer
#define SMEM_BYTES ((2*SA_FLOATS + 2*SB_FLOATS) * 4)   // 106496 -> 2 CTA/SM

// zero row for invalid (-1) gather slots
__device__ __align__(16) float g_zero[64] = {};

// ---------------- helpers ----------------
__device__ __forceinline__ unsigned cvta_smem(const void* p) {
    unsigned r;
    asm("{ .reg .u64 t; cvta.to.shared.u64 t, %1; cvt.u32.u64 %0, t; }"
        : "=r"(r) : "l"(p));
    return r;
}
__device__ __forceinline__ void cpasync16(unsigned dst, const void* src) {
    asm volatile("cp.async.cg.shared.global [%0], [%1], 16;" :: "r"(dst), "l"(src));
}
#define CP_COMMIT() asm volatile("cp.async.commit_group;" ::: "memory")
#define CP_WAIT(n)  asm volatile("cp.async.wait_group %0;" :: "n"(n) : "memory")

__device__ __forceinline__ unsigned cvt_tf32(float f) {
    unsigned t;
    asm("cvt.rna.tf32.f32 %0, %1;" : "=r"(t) : "f"(f));
    return t;
}
__device__ __forceinline__ void ldsm_x4(unsigned addr, unsigned& r0, unsigned& r1,
                                        unsigned& r2, unsigned& r3) {
    asm volatile("ldmatrix.sync.aligned.m8n8.x4.shared.b16 {%0,%1,%2,%3}, [%4];"
                 : "=r"(r0), "=r"(r1), "=r"(r2), "=r"(r3) : "r"(addr));
}
__device__ __forceinline__ void mma_tf32(float& d0, float& d1, float& d2, float& d3,
                                         unsigned a0, unsigned a1, unsigned a2, unsigned a3,
                                         unsigned b0, unsigned b1) {
    asm volatile("mma.sync.aligned.m16n8k8.row.col.f32.tf32.tf32.f32 "
                 "{%0,%1,%2,%3}, {%4,%5,%6,%7}, {%8,%9}, {%0,%1,%2,%3};"
                 : "+f"(d0), "+f"(d1), "+f"(d2), "+f"(d3)
                 : "r"(a0), "r"(a1), "r"(a2), "r"(a3), "r"(b0), "r"(b1));
}

__global__ void __launch_bounds__(NTHREADS, 2)
graphconv_mma(const float* __restrict__ nodes,
              const int*   __restrict__ mapping,
              const float* __restrict__ kern,
              const float* __restrict__ bias,
              float*       __restrict__ out)
{
    extern __shared__ float smem[];
    float* sA = smem;                       // [2][ROWS][APAD]
    float* sB = smem + 2 * SA_FLOATS;       // [2][NC][BPAD] raw fp32
    const unsigned sA_u = cvta_smem(sA);
    const unsigned sB_u = cvta_smem(sB);

    const int tid  = threadIdx.x;
    const int row0 = blockIdx.x * ROWS;

    const int wid = tid >> 5;
    const int l   = tid & 31;
    const int mg  = wid & 3;                // m-group: rows mg*32 .. mg*32+31
    const int ng  = wid >> 2;               // n-group: u  ng*32 .. ng*32+31

    // ---- gather roles: 2 lanes per row, 8 x 16B chunks each ----
    const int gm   = tid >> 1;              // local row 0..127
    const int gl   = tid & 1;
    const int grow = row0 + gm;
    const int bV   = (grow / NV) * NV;

    // ---- A fragment ldmatrix lane address (fixed part) ----
    const unsigned a_lane_rel =
        (unsigned)(((mg * 32 + (l & 15)) * APAD + ((l >> 4) << 2)) * 4);

    // ---- B fragment scalar base (fixed part): conflict-free with BPAD=72 ----
    const int b_lane_rel = (l & 3) * BPAD + ng * 32 + (l >> 2);

    float d[2][4][4];
#pragma unroll
    for (int mt = 0; mt < 2; ++mt)
#pragma unroll
        for (int nt = 0; nt < 4; ++nt)
#pragma unroll
            for (int q = 0; q < 4; ++q) d[mt][nt][q] = 0.f;

    // ---- prologue: region 0, A + B via cp.async, ONE commit group ----
    int m_cur = __ldg(mapping + (size_t)grow * NR);
    {
        const float* src = (m_cur >= 0)
            ? nodes + ((size_t)(bV + m_cur) << 6) + gl * 32 : g_zero;
        unsigned dA = sA_u + (unsigned)((gm * APAD) * 4 + gl * 128);
#pragma unroll
        for (int j = 0; j < 8; ++j) cpasync16(dA + j * 16, src + j * 4);
#pragma unroll
        for (int i = 0; i < 4; ++i) {
            const int c = tid + i * NTHREADS;   // 0..1023
            const int k = c >> 4, ch = c & 15;
            cpasync16(sB_u + (unsigned)((k * BPAD + ch * 4) * 4),
                      kern + k * NU + ch * 4);
        }
        CP_COMMIT();
    }
    int m_nxt = __ldg(mapping + (size_t)grow * NR + 1);

#pragma unroll 1
    for (int r = 0; r < NR; ++r) {
        const int buf = r & 1;

        // ---- stage region r+1 into the other buffer (pure cp.async) ----
        if (r < NR - 1) {
            const int nb = buf ^ 1;
            const float* kg  = kern + (size_t)(r + 1) * (NC * NU);
            const float* src = (m_nxt >= 0)
                ? nodes + ((size_t)(bV + m_nxt) << 6) + gl * 32 : g_zero;
            unsigned dA = sA_u + (unsigned)((nb * SA_FLOATS + gm * APAD) * 4 + gl * 128);
#pragma unroll
            for (int j = 0; j < 8; ++j) cpasync16(dA + j * 16, src + j * 4);
#pragma unroll
            for (int i = 0; i < 4; ++i) {
                const int c = tid + i * NTHREADS;
                const int k = c >> 4, ch = c & 15;
                cpasync16(sB_u + (unsigned)((nb * SB_FLOATS + k * BPAD + ch * 4) * 4),
                          kg + k * NU + ch * 4);
            }
            CP_COMMIT();
            if (r < NR - 2) m_nxt = __ldg(mapping + (size_t)grow * NR + r + 2);
        }

        if (r < NR - 1) { CP_WAIT(1); } else { CP_WAIT(0); }
        __syncthreads();

        const unsigned aaddr0 = sA_u + (unsigned)(buf * SA_FLOATS * 4) + a_lane_rel;
        const float*   Bb     = sB + buf * SB_FLOATS + b_lane_rel;

        // ---- 8 k-steps, register double-buffered fragments, inline B cvt ----
        unsigned a[2][2][4];
        uint2    b[2][4];

        // load ks=0 fragments
#pragma unroll
        for (int mt = 0; mt < 2; ++mt) {
            ldsm_x4(aaddr0 + (unsigned)((mt * 16 * APAD) * 4),
                    a[0][mt][0], a[0][mt][1], a[0][mt][2], a[0][mt][3]);
#pragma unroll
            for (int q = 0; q < 4; ++q)
                a[0][mt][q] = cvt_tf32(__uint_as_float(a[0][mt][q]));
        }
#pragma unroll
        for (int nt = 0; nt < 4; ++nt) {
            b[0][nt].x = cvt_tf32(Bb[nt * 8]);
            b[0][nt].y = cvt_tf32(Bb[4 * BPAD + nt * 8]);
        }

#pragma unroll
        for (int ks = 0; ks < 8; ++ks) {
            const int cur = ks & 1, nxt = cur ^ 1;
            if (ks < 7) {
                const int k1 = (ks + 1) * 8;
#pragma unroll
                for (int mt = 0; mt < 2; ++mt) {
                    ldsm_x4(aaddr0 + (unsigned)((mt * 16 * APAD + k1) * 4),
                            a[nxt][mt][0], a[nxt][mt][1], a[nxt][mt][2], a[nxt][mt][3]);
#pragma unroll
                    for (int q = 0; q < 4; ++q)
                        a[nxt][mt][q] = cvt_tf32(__uint_as_float(a[nxt][mt][q]));
                }
                const float* Bk = Bb + k1 * BPAD;
#pragma unroll
                for (int nt = 0; nt < 4; ++nt) {
                    b[nxt][nt].x = cvt_tf32(Bk[nt * 8]);
                    b[nxt][nt].y = cvt_tf32(Bk[4 * BPAD + nt * 8]);
                }
            }
#pragma unroll
            for (int mt = 0; mt < 2; ++mt)
#pragma unroll
                for (int nt = 0; nt < 4; ++nt)
                    mma_tf32(d[mt][nt][0], d[mt][nt][1], d[mt][nt][2], d[mt][nt][3],
                             a[cur][mt][0], a[cur][mt][1], a[cur][mt][2], a[cur][mt][3],
                             b[cur][nt].x, b[cur][nt].y);
        }
        __syncthreads();   // all warps done reading buf before refill
    }

    // ---- epilogue: bias + relu + STG.64 straight from fragments ----
#pragma unroll
    for (int nt = 0; nt < 4; ++nt) {
        const int u0 = ng * 32 + nt * 8 + 2 * (l & 3);
        float2 bv = *(const float2*)(bias + u0);
#pragma unroll
        for (int mt = 0; mt < 2; ++mt) {
            const int rA = row0 + mg * 32 + mt * 16 + (l >> 2);
            float2 o0, o1;
            o0.x = fmaxf(d[mt][nt][0] + bv.x, 0.f);
            o0.y = fmaxf(d[mt][nt][1] + bv.y, 0.f);
            o1.x = fmaxf(d[mt][nt][2] + bv.x, 0.f);
            o1.y = fmaxf(d[mt][nt][3] + bv.y, 0.f);
            *(float2*)(out + (size_t)rA * NU + u0)       = o0;
            *(float2*)(out + (size_t)(rA + 8) * NU + u0) = o1;
        }
    }
}

extern "C" void kernel_launch(void* const* d_in, const int* in_sizes, int n_in,
                              void* d_out, int out_size) {
    (void)in_sizes; (void)n_in; (void)out_size;
    const float* nodes   = (const float*)d_in[0];
    const int*   mapping = (const int*)d_in[1];
    const float* kern    = (const float*)d_in[2];
    const float* bias    = (const float*)d_in[3];
    float*       out     = (float*)d_out;

    cudaFuncSetAttribute(graphconv_mma,
                         cudaFuncAttributeMaxDynamicSharedMemorySize, SMEM_BYTES);

    int grid = (16 * NV) / ROWS;   // 1250
    graphconv_mma<<<grid, NTHREADS, SMEM_BYTES>>>(nodes, mapping, kern, bias, out);
}

// round 14
// speedup vs baseline: 1.6121x; 1.0147x over previous
#include <cuda_runtime.h>
#include <cstdint>

#define NV 10000
#define NR 8
#define NC 64
#define NU 64
#define ROWS 128
#define NTHREADS 256

// ---- smem layout (bytes) ----
#define OFF_ARAW 0                    // 128 rows * 256B fp32, chunk-XOR swizzled (single buf)
#define OFF_BRAW 32768                // 64 rows * 256B fp32 (single buf)
#define OFF_AH   49152               // fp16 A: 128 rows * 144B (64h + 8 pad)
#define OFF_BH   67584               // fp16 B paired: 32 p-rows * 288B (64 words + 8 pad)
#define SMEM_BYTES (67584 + 9216)    // 76800 -> 2 CTA/SM

__device__ __align__(16) float g_zero[64] = {};

// ---------------- helpers ----------------
__device__ __forceinline__ unsigned cvta_smem(const void* p) {
    unsigned r;
    asm("{ .reg .u64 t; cvta.to.shared.u64 t, %1; cvt.u32.u64 %0, t; }"
        : "=r"(r) : "l"(p));
    return r;
}
__device__ __forceinline__ void cpasync16(unsigned dst, const void* src) {
    asm volatile("cp.async.cg.shared.global [%0], [%1], 16;" :: "r"(dst), "l"(src));
}
#define CP_COMMIT() asm volatile("cp.async.commit_group;" ::: "memory")
#define CP_WAIT0()  asm volatile("cp.async.wait_group 0;" ::: "memory")

// pack {hi,lo} fp32 -> fp16x2 (lo lands in bits[15:0])
__device__ __forceinline__ unsigned f16x2(float hi, float lo) {
    unsigned d;
    asm("cvt.rn.f16x2.f32 %0, %1, %2;" : "=r"(d) : "f"(hi), "f"(lo));
    return d;
}
__device__ __forceinline__ void ldsm_x4(unsigned addr, unsigned& r0, unsigned& r1,
                                        unsigned& r2, unsigned& r3) {
    asm volatile("ldmatrix.sync.aligned.m8n8.x4.shared.b16 {%0,%1,%2,%3}, [%4];"
                 : "=r"(r0), "=r"(r1), "=r"(r2), "=r"(r3) : "r"(addr));
}
__device__ __forceinline__ void mma_f16(float& d0, float& d1, float& d2, float& d3,
                                        unsigned a0, unsigned a1, unsigned a2, unsigned a3,
                                        unsigned b0, unsigned b1) {
    asm volatile("mma.sync.aligned.m16n8k16.row.col.f32.f16.f16.f32 "
                 "{%0,%1,%2,%3}, {%4,%5,%6,%7}, {%8,%9}, {%0,%1,%2,%3};"
                 : "+f"(d0), "+f"(d1), "+f"(d2), "+f"(d3)
                 : "r"(a0), "r"(a1), "r"(a2), "r"(a3), "r"(b0), "r"(b1));
}

__global__ void __launch_bounds__(NTHREADS, 2)
graphconv_f16(const float* __restrict__ nodes,
              const int*   __restrict__ mapping,
              const float* __restrict__ kern,
              const float* __restrict__ bias,
              float*       __restrict__ out)
{
    extern __shared__ char smem[];
    const unsigned smem_u = cvta_smem(smem);

    const int tid  = threadIdx.x;
    const int row0 = blockIdx.x * ROWS;
    const int wid  = tid >> 5;
    const int l    = tid & 31;
    const int mg   = wid & 3;             // m-group: rows mg*32..+31
    const int ng   = wid >> 2;            // n-group: u ng*32..+31

    // gather roles: 2 lanes per row
    const int gm   = tid >> 1;            // local row 0..127
    const int gl   = tid & 1;
    const int grow = row0 + gm;
    const int bV   = (grow / NV) * NV;

    float d[2][4][4];
#pragma unroll
    for (int mt = 0; mt < 2; ++mt)
#pragma unroll
        for (int nt = 0; nt < 4; ++nt)
#pragma unroll
            for (int q = 0; q < 4; ++q) d[mt][nt][q] = 0.f;

    // ---- prologue: stage region 0 (A gather + B raw) ----
    int m_cur = __ldg(mapping + (size_t)grow * NR);
    {
        const float* src = (m_cur >= 0) ? nodes + ((size_t)(bV + m_cur) << 6) : g_zero;
        unsigned dA = smem_u + OFF_ARAW + (unsigned)(gm * 256);
#pragma unroll
        for (int j = 0; j < 8; ++j) {
            const int jj = gl * 8 + j;
            cpasync16(dA + (unsigned)((jj ^ (gm & 7)) << 4), src + jj * 4);
        }
#pragma unroll
        for (int i = 0; i < 4; ++i) {
            const int c = tid + i * NTHREADS;    // 0..1023
            const int k = c >> 4, ch = c & 15;
            cpasync16(smem_u + OFF_BRAW + (unsigned)(k * 256 + ch * 16),
                      kern + k * NU + ch * 4);
        }
        CP_COMMIT();
    }
    int m_nxt = __ldg(mapping + (size_t)grow * NR + 1);

    // conversion role constants
    const int crr = tid >> 1;             // A convert: row 0..127
    const int chh = tid & 1;              // half of row (32 floats)

#pragma unroll 1
    for (int r = 0; r < NR; ++r) {
        CP_WAIT0();
        __syncthreads();                  // raw r ready; f16 bufs free

        // ---- convert A raw fp32 -> fp16 [128][72h] ----
        {
            unsigned w[16];
#pragma unroll
            for (int c = 0; c < 8; ++c) {
                const int chunk = chh * 8 + c;
                float4 v = *(const float4*)(smem + OFF_ARAW + crr * 256
                                            + ((chunk ^ (crr & 7)) << 4));
                w[2*c]   = f16x2(v.y, v.x);
                w[2*c+1] = f16x2(v.w, v.z);
            }
            char* dst = smem + OFF_AH + crr * 144 + chh * 64;
#pragma unroll
            for (int q = 0; q < 4; ++q)
                *(uint4*)(dst + q * 16) = make_uint4(w[4*q], w[4*q+1], w[4*q+2], w[4*q+3]);
        }
        // ---- convert B raw fp32 [k][u] -> paired fp16 [p=k/2][u] (288B rows) ----
        {
#pragma unroll
            for (int i = 0; i < 8; ++i) {
                const int j = tid + i * NTHREADS;   // 0..2047
                const int p = j >> 6, u = j & 63;
                float f0 = *(const float*)(smem + OFF_BRAW + (2*p) * 256 + u * 4);
                float f1 = *(const float*)(smem + OFF_BRAW + (2*p+1) * 256 + u * 4);
                *(unsigned*)(smem + OFF_BH + p * 288 + u * 4) = f16x2(f1, f0);
            }
        }
        __syncthreads();                  // f16 ready; raw bufs free

        // ---- stage region r+1 into raw bufs (fire-and-forget) ----
        if (r < NR - 1) {
            const float* kg  = kern + (size_t)(r + 1) * (NC * NU);
            const float* src = (m_nxt >= 0) ? nodes + ((size_t)(bV + m_nxt) << 6) : g_zero;
            unsigned dA = smem_u + OFF_ARAW + (unsigned)(gm * 256);
#pragma unroll
            for (int j = 0; j < 8; ++j) {
                const int jj = gl * 8 + j;
                cpasync16(dA + (unsigned)((jj ^ (gm & 7)) << 4), src + jj * 4);
            }
#pragma unroll
            for (int i = 0; i < 4; ++i) {
                const int c = tid + i * NTHREADS;
                const int k = c >> 4, ch = c & 15;
                cpasync16(smem_u + OFF_BRAW + (unsigned)(k * 256 + ch * 16),
                          kg + k * NU + ch * 4);
            }
            CP_COMMIT();
            if (r < NR - 2) m_nxt = __ldg(mapping + (size_t)grow * NR + r + 2);
        }

        // ---- compute: 4 k-steps of m16n8k16 fp16 ----
        const unsigned a_ld = smem_u + OFF_AH
            + (unsigned)((mg * 32 + (l & 15)) * 144 + (l >> 4) * 16);
        const char* Bh = smem + OFF_BH + (l & 3) * 288 + (ng * 32 + (l >> 2)) * 4;

#pragma unroll
        for (int ks = 0; ks < 4; ++ks) {
            unsigned b0[4], b1[4];
#pragma unroll
            for (int nt = 0; nt < 4; ++nt) {
                b0[nt] = *(const unsigned*)(Bh + (ks * 8)     * 288 + nt * 32);
                b1[nt] = *(const unsigned*)(Bh + (ks * 8 + 4) * 288 + nt * 32);
            }
#pragma unroll
            for (int mt = 0; mt < 2; ++mt) {
                unsigned a0, a1, a2, a3;
                ldsm_x4(a_ld + (unsigned)(mt * 16 * 144 + ks * 32), a0, a1, a2, a3);
#pragma unroll
                for (int nt = 0; nt < 4; ++nt)
                    mma_f16(d[mt][nt][0], d[mt][nt][1], d[mt][nt][2], d[mt][nt][3],
                            a0, a1, a2, a3, b0[nt], b1[nt]);
            }
        }
        __syncthreads();   // compute done before next conversion overwrites f16 bufs
    }

    // ---- epilogue: bias + relu + STG.64 straight from fragments ----
#pragma unroll
    for (int nt = 0; nt < 4; ++nt) {
        const int u0 = ng * 32 + nt * 8 + 2 * (l & 3);
        float2 bv = *(const float2*)(bias + u0);
#pragma unroll
        for (int mt = 0; mt < 2; ++mt) {
            const int rA = row0 + mg * 32 + mt * 16 + (l >> 2);
            float2 o0, o1;
            o0.x = fmaxf(d[mt][nt][0] + bv.x, 0.f);
            o0.y = fmaxf(d[mt][nt][1] + bv.y, 0.f);
            o1.x = fmaxf(d[mt][nt][2] + bv.x, 0.f);
            o1.y = fmaxf(d[mt][nt][3] + bv.y, 0.f);
            *(float2*)(out + (size_t)rA * NU + u0)       = o0;
            *(float2*)(out + (size_t)(rA + 8) * NU + u0) = o1;
        }
    }
}

extern "C" void kernel_launch(void* const* d_in, const int* in_sizes, int n_in,
                              void* d_out, int out_size) {
    (void)in_sizes; (void)n_in; (void)out_size;
    const float* nodes   = (const float*)d_in[0];
    const int*   mapping = (const int*)d_in[1];
    const float* kern    = (const float*)d_in[2];
    const float* bias    = (const float*)d_in[3];
    float*       out     = (float*)d_out;

    cudaFuncSetAttribute(graphconv_f16,
                         cudaFuncAttributeMaxDynamicSharedMemorySize, SMEM_BYTES);

    int grid = (16 * NV) / ROWS;   // 1250
    graphconv_f16<<<grid, NTHREADS, SMEM_BYTES>>>(nodes, mapping, kern, bias, out);
}

// round 15
// speedup vs baseline: 3.4998x; 2.1710x over previous
#include <cuda_runtime.h>
#include <cuda_fp16.h>
#include <cstdint>

#define NV 10000
#define NB 16
#define NR 8
#define NC 64
#define NU 64
#define ROWS 64
#define NTHREADS 256
#define NROWS_TOT (NB * NV)          // 160000

// ---- device-global scratch (zero-init; row NROWS_TOT stays zero for m=-1) ----
__device__ __align__(16) __half    g_nodes_h[(NROWS_TOT + 8) * NC];   // ~20.5MB
__device__ __align__(16) unsigned  g_kern_pair[NR * 32 * 64];         // paired f16

// ---- smem layout (bytes) ----
#define A_BUF 8192                   // 64 rows * 128B f16, XOR-swizzled
#define B_BUF 9216                   // 32 p-rows * 288B (72 words, conflict-free)
#define OFF_A 0
#define OFF_B (2 * A_BUF)            // 16384
#define SMEM_BYTES (OFF_B + 2 * B_BUF)   // 34816 -> 4+ CTA/SM

// ---------------- helpers ----------------
__device__ __forceinline__ unsigned cvta_smem(const void* p) {
    unsigned r;
    asm("{ .reg .u64 t; cvta.to.shared.u64 t, %1; cvt.u32.u64 %0, t; }"
        : "=r"(r) : "l"(p));
    return r;
}
__device__ __forceinline__ void cpasync16(unsigned dst, const void* src) {
    asm volatile("cp.async.cg.shared.global [%0], [%1], 16;" :: "r"(dst), "l"(src));
}
#define CP_COMMIT() asm volatile("cp.async.commit_group;" ::: "memory")
#define CP_WAIT(n)  asm volatile("cp.async.wait_group %0;" :: "n"(n) : "memory")

__device__ __forceinline__ unsigned f16x2(float hi, float lo) {
    unsigned d;
    asm("cvt.rn.f16x2.f32 %0, %1, %2;" : "=r"(d) : "f"(hi), "f"(lo));
    return d;
}
__device__ __forceinline__ void ldsm_x4(unsigned addr, unsigned& r0, unsigned& r1,
                                        unsigned& r2, unsigned& r3) {
    asm volatile("ldmatrix.sync.aligned.m8n8.x4.shared.b16 {%0,%1,%2,%3}, [%4];"
                 : "=r"(r0), "=r"(r1), "=r"(r2), "=r"(r3) : "r"(addr));
}
__device__ __forceinline__ void mma_f16(float& d0, float& d1, float& d2, float& d3,
                                        unsigned a0, unsigned a1, unsigned a2, unsigned a3,
                                        unsigned b0, unsigned b1) {
    asm volatile("mma.sync.aligned.m16n8k16.row.col.f32.f16.f16.f32 "
                 "{%0,%1,%2,%3}, {%4,%5,%6,%7}, {%8,%9}, {%0,%1,%2,%3};"
                 : "+f"(d0), "+f"(d1), "+f"(d2), "+f"(d3)
                 : "r"(a0), "r"(a1), "r"(a2), "r"(a3), "r"(b0), "r"(b1));
}

// ---------------- pre-pass kernels ----------------
__global__ void conv_nodes(const float* __restrict__ nodes) {
    const int total = NROWS_TOT * NC / 4;      // float4 count
    const float4* src = (const float4*)nodes;
    uint2* dst = (uint2*)g_nodes_h;
    for (int i = blockIdx.x * blockDim.x + threadIdx.x; i < total;
         i += gridDim.x * blockDim.x) {
        float4 v = src[i];
        uint2 o;
        o.x = f16x2(v.y, v.x);
        o.y = f16x2(v.w, v.z);
        dst[i] = o;
    }
}

__global__ void conv_kern(const float* __restrict__ kern) {
    const int total = NR * 32 * 64;            // paired words
    for (int i = blockIdx.x * blockDim.x + threadIdx.x; i < total;
         i += gridDim.x * blockDim.x) {
        const int u = i & 63, p = (i >> 6) & 31, r = i >> 11;
        float f0 = kern[(r * 64 + 2 * p)     * NU + u];
        float f1 = kern[(r * 64 + 2 * p + 1) * NU + u];
        g_kern_pair[i] = f16x2(f1, f0);        // low half = even k
    }
}

// ---------------- main kernel ----------------
__global__ void __launch_bounds__(NTHREADS, 4)
graphconv_main(const int* __restrict__ mapping,
               const float* __restrict__ bias,
               float* __restrict__ out)
{
    extern __shared__ char smem[];
    const unsigned smem_u = cvta_smem(smem);

    const int tid  = threadIdx.x;
    const int row0 = blockIdx.x * ROWS;
    const int wid  = tid >> 5;
    const int l    = tid & 31;
    const int mg   = wid & 1;            // m-group: rows mg*32..+31
    const int ng   = wid >> 1;           // n-group: u ng*16..+15

    // gather roles: 4 lanes per row, 2 x 16B chunks each
    const int gm   = tid >> 2;           // local row 0..63
    const int gl   = tid & 3;
    const int grow = row0 + gm;
    const int bV   = (grow / NV) * NV;

    float d[2][2][4];
#pragma unroll
    for (int mt = 0; mt < 2; ++mt)
#pragma unroll
        for (int nt = 0; nt < 2; ++nt)
#pragma unroll
            for (int q = 0; q < 4; ++q) d[mt][nt][q] = 0.f;

    // ---- prologue: stage region 0 ----
    int m_cur = __ldg(mapping + (size_t)grow * NR);
    {
        const int srow = (m_cur >= 0) ? (bV + m_cur) : NROWS_TOT;
        const char* src = (const char*)(g_nodes_h + (size_t)srow * NC);
        unsigned dA = smem_u + OFF_A + (unsigned)(gm * 128);
#pragma unroll
        for (int j = 0; j < 2; ++j) {
            const int jj = gl * 2 + j;
            cpasync16(dA + (unsigned)((jj ^ (gm & 7)) << 4), src + jj * 16);
        }
#pragma unroll
        for (int i = 0; i < 2; ++i) {
            const int c = tid + i * NTHREADS;   // 0..511
            const int p = c >> 4, ch = c & 15;
            cpasync16(smem_u + OFF_B + (unsigned)(p * 288 + ch * 16),
                      (const char*)g_kern_pair + (p * 64 + ch * 4) * 4);
        }
        CP_COMMIT();
    }
    int m_nxt = __ldg(mapping + (size_t)grow * NR + 1);

#pragma unroll 1
    for (int r = 0; r < NR; ++r) {
        const int buf = r & 1;

        // ---- stage region r+1 into the other buffer ----
        if (r < NR - 1) {
            const int nb = buf ^ 1;
            const int srow = (m_nxt >= 0) ? (bV + m_nxt) : NROWS_TOT;
            const char* src = (const char*)(g_nodes_h + (size_t)srow * NC);
            unsigned dA = smem_u + OFF_A + (unsigned)(nb * A_BUF + gm * 128);
#pragma unroll
            for (int j = 0; j < 2; ++j) {
                const int jj = gl * 2 + j;
                cpasync16(dA + (unsigned)((jj ^ (gm & 7)) << 4), src + jj * 16);
            }
            const char* kg = (const char*)g_kern_pair + (r + 1) * 2048 * 4;
#pragma unroll
            for (int i = 0; i < 2; ++i) {
                const int c = tid + i * NTHREADS;
                const int p = c >> 4, ch = c & 15;
                cpasync16(smem_u + OFF_B + (unsigned)(nb * B_BUF + p * 288 + ch * 16),
                          kg + (p * 64 + ch * 4) * 4);
            }
            CP_COMMIT();
            if (r < NR - 2) m_nxt = __ldg(mapping + (size_t)grow * NR + r + 2);
        }

        if (r < NR - 1) { CP_WAIT(1); } else { CP_WAIT(0); }
        __syncthreads();

        // ---- compute: 4 k-steps of m16n8k16 fp16 ----
        const unsigned a_base = smem_u + OFF_A
            + (unsigned)(buf * A_BUF + (mg * 32 + (l & 15)) * 128);
        const int rx = l & 7;
        const char* Bh = smem + OFF_B + buf * B_BUF
            + (l & 3) * 288 + (ng * 16 + (l >> 2)) * 4;

#pragma unroll
        for (int ks = 0; ks < 4; ++ks) {
            unsigned b0[2], b1[2];
#pragma unroll
            for (int nt = 0; nt < 2; ++nt) {
                b0[nt] = *(const unsigned*)(Bh + (ks * 8)     * 288 + nt * 32);
                b1[nt] = *(const unsigned*)(Bh + (ks * 8 + 4) * 288 + nt * 32);
            }
#pragma unroll
            for (int mt = 0; mt < 2; ++mt) {
                unsigned a0, a1, a2, a3;
                ldsm_x4(a_base + (unsigned)(mt * 16 * 128)
                        + (unsigned)((((ks * 2 + (l >> 4)) ^ rx) << 4)),
                        a0, a1, a2, a3);
#pragma unroll
                for (int nt = 0; nt < 2; ++nt)
                    mma_f16(d[mt][nt][0], d[mt][nt][1], d[mt][nt][2], d[mt][nt][3],
                            a0, a1, a2, a3, b0[nt], b1[nt]);
            }
        }
        __syncthreads();   // done reading buf before refill
    }

    // ---- epilogue: bias + relu + STG.64 straight from fragments ----
#pragma unroll
    for (int nt = 0; nt < 2; ++nt) {
        const int u0 = ng * 16 + nt * 8 + 2 * (l & 3);
        float2 bv = *(const float2*)(bias + u0);
#pragma unroll
        for (int mt = 0; mt < 2; ++mt) {
            const int rA = row0 + mg * 32 + mt * 16 + (l >> 2);
            float2 o0, o1;
            o0.x = fmaxf(d[mt][nt][0] + bv.x, 0.f);
            o0.y = fmaxf(d[mt][nt][1] + bv.y, 0.f);
            o1.x = fmaxf(d[mt][nt][2] + bv.x, 0.f);
            o1.y = fmaxf(d[mt][nt][3] + bv.y, 0.f);
            *(float2*)(out + (size_t)rA * NU + u0)       = o0;
            *(float2*)(out + (size_t)(rA + 8) * NU + u0) = o1;
        }
    }
}

extern "C" void kernel_launch(void* const* d_in, const int* in_sizes, int n_in,
                              void* d_out, int out_size) {
    (void)in_sizes; (void)n_in; (void)out_size;
    const float* nodes   = (const float*)d_in[0];
    const int*   mapping = (const int*)d_in[1];
    const float* kern    = (const float*)d_in[2];
    const float* bias    = (const float*)d_in[3];
    float*       out     = (float*)d_out;

    conv_nodes<<<2048, 256>>>(nodes);
    conv_kern<<<64, 256>>>(kern);

    cudaFuncSetAttribute(graphconv_main,
                         cudaFuncAttributeMaxDynamicSharedMemorySize, SMEM_BYTES);
    int grid = NROWS_TOT / ROWS;   // 2500
    graphconv_main<<<grid, NTHREADS, SMEM_BYTES>>>(mapping, bias, out);
}